// round 1
// baseline (speedup 1.0000x reference)
#include <cuda_runtime.h>

// MonarchAttention on GB300 — fp32, batched 64x64x64 smem GEMMs.
// B=4,H=16 -> BH=64 heads; N=4096, D=64, b=m=64, STEPS=3.
//
// Layouts (all fp32):
//   Q/K/V   : [bh][blk i][s][d]      (token = i*64+s)
//   g_L     : [bh][s][i][j]
//   g_qbar  : [bh][j][s][d]
//   g_kbar  : [bh][s][j][d]
//   g_vbar  : [bh][s][j][d]
//   g_ent   : [bh][s][j]
//   g_qmean : [bh][s][d]

#define BHn   64
#define SCALE 0.125f   // 1/sqrt(64)

__device__ float g_qmean[BHn * 64 * 64];
__device__ float g_ent  [BHn * 64 * 64];
__device__ float g_L    [16777216];
__device__ float g_qbar [16777216];
__device__ float g_kbar [16777216];
__device__ float g_vbar [16777216];

// ---------------------------------------------------------------------------
// helpers
// ---------------------------------------------------------------------------
__device__ __forceinline__ float redmax16(float v) {
#pragma unroll
    for (int m = 8; m; m >>= 1) v = fmaxf(v, __shfl_xor_sync(0xffffffffu, v, m));
    return v;
}
__device__ __forceinline__ float redsum16(float v) {
#pragma unroll
    for (int m = 8; m; m >>= 1) v += __shfl_xor_sync(0xffffffffu, v, m);
    return v;
}

// C[r][c] += sum_k A[k][r]*B[k][c]; both reduction-major, float4 loads.
template <int SA, int SB>
__device__ __forceinline__ void mm16(const float* __restrict__ sA,
                                     const float* __restrict__ sB,
                                     int ty4, int tx4, float acc[4][4]) {
#pragma unroll 8
    for (int k = 0; k < 64; ++k) {
        float4 av = *reinterpret_cast<const float4*>(sA + k * SA + ty4);
        float4 bv = *reinterpret_cast<const float4*>(sB + k * SB + tx4);
        const float a[4] = {av.x, av.y, av.z, av.w};
        const float b[4] = {bv.x, bv.y, bv.z, bv.w};
#pragma unroll
        for (int r = 0; r < 4; ++r)
#pragma unroll
            for (int c = 0; c < 4; ++c)
                acc[r][c] = fmaf(a[r], b[c], acc[r][c]);
    }
}

// same but A has stride 65 and is loaded scalar (transposed-from-registers arrays)
__device__ __forceinline__ void mm16_sa65(const float* __restrict__ sA,
                                          const float* __restrict__ sB,
                                          int ty4, int tx4, float acc[4][4]) {
#pragma unroll 8
    for (int k = 0; k < 64; ++k) {
        const float* ap = sA + k * 65 + ty4;
        float4 bv = *reinterpret_cast<const float4*>(sB + (k << 6) + tx4);
        const float a[4] = {ap[0], ap[1], ap[2], ap[3]};
        const float b[4] = {bv.x, bv.y, bv.z, bv.w};
#pragma unroll
        for (int r = 0; r < 4; ++r)
#pragma unroll
            for (int c = 0; c < 4; ++c)
                acc[r][c] = fmaf(a[r], b[c], acc[r][c]);
    }
}

// ---------------------------------------------------------------------------
// A0: qmean[bh][s][d] = mean_i Q[bh][i][s][d]   (step-0 qbar is j-independent)
// grid 1024, 256 thr
// ---------------------------------------------------------------------------
__global__ void qmean_kernel(const float* __restrict__ Q) {
    int bid = blockIdx.x;
    int bh = bid >> 4;
    int s = ((bid & 15) << 2) + (threadIdx.x >> 6);
    int d = threadIdx.x & 63;
    const float* base = Q + bh * 262144 + s * 64 + d;
    float acc = 0.f;
#pragma unroll 16
    for (int i = 0; i < 64; ++i) acc += base[i * 4096];
    g_qmean[(bh << 6 | s) * 64 + d] = acc * (1.0f / 64.0f);
}

// ---------------------------------------------------------------------------
// A: per (bh,s): w[j] = sum_i L[i][j]; qbar[j][d] = (sum_i L[i][j]Q[i][d])/w[j]
// grid 4096, 256 thr, smem 33024B
// ---------------------------------------------------------------------------
__global__ void qbar_kernel(const float* __restrict__ Q) {
    int bid = blockIdx.x;
    int bh = bid >> 6, s = bid & 63;
    extern __shared__ float sm[];
    float* sL = sm;           // [i][j] stride 64 (reduction i major already)
    float* sQ = sm + 4096;    // [i][d] stride 64
    float* sw = sm + 8192;    // [64] 1/w
    int tid = threadIdx.x;

    const float4* Lb = reinterpret_cast<const float4*>(g_L + ((bh << 6 | s) << 12));
#pragma unroll
    for (int r = 0; r < 4; ++r) {
        int l4 = (r << 8) + tid;
        reinterpret_cast<float4*>(sL)[l4] = Lb[l4];
    }
    const float* Qb = Q + bh * 262144 + s * 64;
#pragma unroll
    for (int r = 0; r < 4; ++r) {
        int l4 = (r << 8) + tid;
        int i = l4 >> 4, d4 = (l4 & 15) << 2;
        reinterpret_cast<float4*>(sQ)[l4] =
            *reinterpret_cast<const float4*>(Qb + i * 4096 + d4);
    }
    __syncthreads();
    if (tid < 64) {
        float acc = 0.f;
#pragma unroll 8
        for (int i = 0; i < 64; ++i) acc += sL[(i << 6) + tid];
        sw[tid] = 1.0f / acc;
    }
    __syncthreads();

    int tx = tid & 15, ty = tid >> 4;
    float acc[4][4] = {};
    mm16<64, 64>(sL, sQ, ty << 2, tx << 2, acc);

    float* ob = g_qbar + bh * 262144 + s * 64 + (tx << 2);
#pragma unroll
    for (int rr = 0; rr < 4; ++rr) {
        int j = (ty << 2) + rr;
        float w = sw[j];
        float4 o = make_float4(acc[rr][0] * w, acc[rr][1] * w, acc[rr][2] * w, acc[rr][3] * w);
        *reinterpret_cast<float4*>(ob + j * 4096) = o;
    }
}

// ---------------------------------------------------------------------------
// B: per (bh,j): S=scale*qbar_j K_j^T; R=softmax_t(S); ent; kbar=R K; (vbar=R V)
// grid 4096, 256 thr, smem 84224B
// ---------------------------------------------------------------------------
__global__ void bstep_kernel(const float* __restrict__ Kg, const float* __restrict__ Vg,
                             int use_qmean, int do_vbar) {
    int bid = blockIdx.x;
    int bh = bid >> 6, j = bid & 63;
    extern __shared__ float sm[];
    float* sQbT = sm;             // [d][s] stride 68
    float* sKT  = sm + 4352;      // [d][t] stride 68
    float* sK   = sm + 8704;      // [t][d] stride 64
    float* sV   = sm + 12800;     // [t][d] stride 64
    float* sRT  = sm + 16896;     // [t][s] stride 65
    int tid = threadIdx.x;

    const float* Kb = Kg + bh * 262144 + j * 4096;
#pragma unroll
    for (int r = 0; r < 16; ++r) {
        int lin = (r << 8) + tid;
        int t = lin >> 6, d = lin & 63;
        float v = Kb[lin];
        sK[lin] = v;
        sKT[d * 68 + t] = v;
    }
    const float* qb = use_qmean ? (g_qmean + (bh << 12))
                                : (g_qbar + bh * 262144 + j * 4096);
#pragma unroll
    for (int r = 0; r < 16; ++r) {
        int lin = (r << 8) + tid;
        int s = lin >> 6, d = lin & 63;
        sQbT[d * 68 + s] = qb[lin];
    }
    if (do_vbar) {
        const float* Vb = Vg + bh * 262144 + j * 4096;
#pragma unroll
        for (int r = 0; r < 4; ++r) {
            int l4 = (r << 8) + tid;
            reinterpret_cast<float4*>(sV)[l4] = reinterpret_cast<const float4*>(Vb)[l4];
        }
    }
    __syncthreads();

    int tx = tid & 15, ty = tid >> 4;
    int tx4 = tx << 2, ty4 = ty << 2;

    float S[4][4] = {};
    mm16<68, 68>(sQbT, sKT, ty4, tx4, S);

    // softmax over t (across tx), R + entropy
    float R[4][4];
#pragma unroll
    for (int rr = 0; rr < 4; ++rr) {
        float mx = -1e30f;
#pragma unroll
        for (int cc = 0; cc < 4; ++cc) { S[rr][cc] *= SCALE; mx = fmaxf(mx, S[rr][cc]); }
        mx = redmax16(mx);
        float p[4], sum = 0.f;
#pragma unroll
        for (int cc = 0; cc < 4; ++cc) { p[cc] = __expf(S[rr][cc] - mx); sum += p[cc]; }
        sum = redsum16(sum);
        float inv = 1.0f / sum;
        float lsum = __logf(sum);
        float e = 0.f;
#pragma unroll
        for (int cc = 0; cc < 4; ++cc) {
            float rv = p[cc] * inv;
            float lr = S[rr][cc] - mx - lsum;
            e += rv * lr;
            R[rr][cc] = rv;
        }
        e = redsum16(e);
        if (tx == 0) g_ent[((bh << 6) + ty4 + rr) * 64 + j] = -e;
    }
#pragma unroll
    for (int rr = 0; rr < 4; ++rr)
#pragma unroll
        for (int cc = 0; cc < 4; ++cc)
            sRT[(tx4 + cc) * 65 + ty4 + rr] = R[rr][cc];
    __syncthreads();

    // kbar[s][d] = sum_t R[s][t] K[t][d]
    float acc[4][4] = {};
    mm16_sa65(sRT, sK, ty4, tx4, acc);
#pragma unroll
    for (int rr = 0; rr < 4; ++rr) {
        int s = ty4 + rr;
        *reinterpret_cast<float4*>(g_kbar + ((bh << 6 | s) << 12) + (j << 6) + tx4) =
            make_float4(acc[rr][0], acc[rr][1], acc[rr][2], acc[rr][3]);
    }

    if (do_vbar) {
        float av[4][4] = {};
        mm16_sa65(sRT, sV, ty4, tx4, av);
#pragma unroll
        for (int rr = 0; rr < 4; ++rr) {
            int s = ty4 + rr;
            *reinterpret_cast<float4*>(g_vbar + ((bh << 6 | s) << 12) + (j << 6) + tx4) =
                make_float4(av[rr][0], av[rr][1], av[rr][2], av[rr][3]);
        }
    }
}

// ---------------------------------------------------------------------------
// C: per (bh,s): SL = scale*Q kbar^T + ent; L = softmax_j; write L or out=L vbar
// grid 4096, 256 thr, smem 68096B
// ---------------------------------------------------------------------------
__global__ void cstep_kernel(const float* __restrict__ Qg, float* __restrict__ out,
                             int is_final) {
    int bid = blockIdx.x;
    int bh = bid >> 6, s = bid & 63;
    extern __shared__ float sm[];
    float* sQT  = sm;             // [d][i] stride 68
    float* sKbT = sm + 4352;      // [d][j] stride 68
    float* sLT  = sm + 8704;      // [j][i] stride 65 (final only)
    float* sVb  = sm + 12864;     // [j][d] stride 64 (final only)
    float* sEnt = sm + 16960;     // [64]
    int tid = threadIdx.x;

    const float* Qb = Qg + bh * 262144 + s * 64;
#pragma unroll
    for (int r = 0; r < 16; ++r) {
        int lin = (r << 8) + tid;
        int i = lin >> 6, d = lin & 63;
        sQT[d * 68 + i] = Qb[i * 4096 + d];
    }
    const float* kb = g_kbar + ((bh << 6 | s) << 12);
#pragma unroll
    for (int r = 0; r < 16; ++r) {
        int lin = (r << 8) + tid;
        int jj = lin >> 6, d = lin & 63;
        sKbT[d * 68 + jj] = kb[lin];
    }
    if (is_final) {
        const float* vb = g_vbar + ((bh << 6 | s) << 12);
#pragma unroll
        for (int r = 0; r < 4; ++r) {
            int l4 = (r << 8) + tid;
            reinterpret_cast<float4*>(sVb)[l4] = reinterpret_cast<const float4*>(vb)[l4];
        }
    }
    if (tid < 64) sEnt[tid] = g_ent[((bh << 6) + s) * 64 + tid];
    __syncthreads();

    int tx = tid & 15, ty = tid >> 4;
    int tx4 = tx << 2, ty4 = ty << 2;

    float S[4][4] = {};
    mm16<68, 68>(sQT, sKbT, ty4, tx4, S);

    float ev[4];
#pragma unroll
    for (int cc = 0; cc < 4; ++cc) ev[cc] = sEnt[tx4 + cc];

    float L[4][4];
#pragma unroll
    for (int rr = 0; rr < 4; ++rr) {
        float mx = -1e30f;
#pragma unroll
        for (int cc = 0; cc < 4; ++cc) {
            S[rr][cc] = S[rr][cc] * SCALE + ev[cc];
            mx = fmaxf(mx, S[rr][cc]);
        }
        mx = redmax16(mx);
        float sum = 0.f;
#pragma unroll
        for (int cc = 0; cc < 4; ++cc) { L[rr][cc] = __expf(S[rr][cc] - mx); sum += L[rr][cc]; }
        sum = redsum16(sum);
        float inv = 1.0f / sum;
#pragma unroll
        for (int cc = 0; cc < 4; ++cc) L[rr][cc] *= inv;
    }

    if (!is_final) {
        float* lb = g_L + ((bh << 6 | s) << 12) + tx4;
#pragma unroll
        for (int rr = 0; rr < 4; ++rr) {
            int i = ty4 + rr;
            *reinterpret_cast<float4*>(lb + (i << 6)) =
                make_float4(L[rr][0], L[rr][1], L[rr][2], L[rr][3]);
        }
    } else {
#pragma unroll
        for (int rr = 0; rr < 4; ++rr)
#pragma unroll
            for (int cc = 0; cc < 4; ++cc)
                sLT[(tx4 + cc) * 65 + ty4 + rr] = L[rr][cc];
        __syncthreads();
        float acc[4][4] = {};
        mm16_sa65(sLT, sVb, ty4, tx4, acc);
        float* ob = out + bh * 262144 + s * 64 + tx4;
#pragma unroll
        for (int rr = 0; rr < 4; ++rr) {
            int i = ty4 + rr;
            *reinterpret_cast<float4*>(ob + i * 4096) =
                make_float4(acc[rr][0], acc[rr][1], acc[rr][2], acc[rr][3]);
        }
    }
}

// ---------------------------------------------------------------------------
extern "C" void kernel_launch(void* const* d_in, const int* in_sizes, int n_in,
                              void* d_out, int out_size) {
    const float* Q = (const float*)d_in[0];
    const float* K = (const float*)d_in[1];
    const float* V = (const float*)d_in[2];
    float* out = (float*)d_out;

    const int SM_A = 8256 * 4;    // 33024
    const int SM_B = 21056 * 4;   // 84224
    const int SM_C = 17024 * 4;   // 68096
    cudaFuncSetAttribute(qbar_kernel,  cudaFuncAttributeMaxDynamicSharedMemorySize, SM_A);
    cudaFuncSetAttribute(bstep_kernel, cudaFuncAttributeMaxDynamicSharedMemorySize, SM_B);
    cudaFuncSetAttribute(cstep_kernel, cudaFuncAttributeMaxDynamicSharedMemorySize, SM_C);

    // step 0
    qmean_kernel<<<1024, 256>>>(Q);
    bstep_kernel<<<4096, 256, SM_B>>>(K, V, 1, 0);
    cstep_kernel<<<4096, 256, SM_C>>>(Q, out, 0);
    // step 1
    qbar_kernel<<<4096, 256, SM_A>>>(Q);
    bstep_kernel<<<4096, 256, SM_B>>>(K, V, 0, 0);
    cstep_kernel<<<4096, 256, SM_C>>>(Q, out, 0);
    // step 2 (B also produces vbar; C fuses final output)
    qbar_kernel<<<4096, 256, SM_A>>>(Q);
    bstep_kernel<<<4096, 256, SM_B>>>(K, V, 0, 1);
    cstep_kernel<<<4096, 256, SM_C>>>(Q, out, 1);
}

// round 2
// speedup vs baseline: 1.0007x; 1.0007x over previous
#include <cuda_runtime.h>

// MonarchAttention on GB300 — fp32, batched 64x64x64 smem GEMMs.
// B=4,H=16 -> BH=64 heads; N=4096, D=64, b=m=64, STEPS=3.
//
// Layouts (all fp32):
//   Q/K/V   : [bh][blk i][s][d]      (token = i*64+s)
//   g_L     : [bh][s][i][j]
//   g_qbar  : [bh][j][s][d]
//   g_kbar  : [bh][s][j][d]
//   g_vbar  : [bh][s][j][d]
//   g_ent   : [bh][s][j]
//   g_qmean : [bh][s][d]

#define BHn   64
#define SCALE 0.125f   // 1/sqrt(64)

__device__ float g_qmean[BHn * 64 * 64];
__device__ float g_ent  [BHn * 64 * 64];
__device__ float g_L    [16777216];
__device__ float g_qbar [16777216];
__device__ float g_kbar [16777216];
__device__ float g_vbar [16777216];

// ---------------------------------------------------------------------------
// helpers
// ---------------------------------------------------------------------------
__device__ __forceinline__ float redmax16(float v) {
#pragma unroll
    for (int m = 8; m; m >>= 1) v = fmaxf(v, __shfl_xor_sync(0xffffffffu, v, m));
    return v;
}
__device__ __forceinline__ float redsum16(float v) {
#pragma unroll
    for (int m = 8; m; m >>= 1) v += __shfl_xor_sync(0xffffffffu, v, m);
    return v;
}

// C[r][c] += sum_k A[k][r]*B[k][c]; both reduction-major, float4 loads.
template <int SA, int SB>
__device__ __forceinline__ void mm16(const float* __restrict__ sA,
                                     const float* __restrict__ sB,
                                     int ty4, int tx4, float acc[4][4]) {
#pragma unroll 8
    for (int k = 0; k < 64; ++k) {
        float4 av = *reinterpret_cast<const float4*>(sA + k * SA + ty4);
        float4 bv = *reinterpret_cast<const float4*>(sB + k * SB + tx4);
        const float a[4] = {av.x, av.y, av.z, av.w};
        const float b[4] = {bv.x, bv.y, bv.z, bv.w};
#pragma unroll
        for (int r = 0; r < 4; ++r)
#pragma unroll
            for (int c = 0; c < 4; ++c)
                acc[r][c] = fmaf(a[r], b[c], acc[r][c]);
    }
}

// same but A has stride 65 and is loaded scalar (transposed-from-registers arrays)
__device__ __forceinline__ void mm16_sa65(const float* __restrict__ sA,
                                          const float* __restrict__ sB,
                                          int ty4, int tx4, float acc[4][4]) {
#pragma unroll 8
    for (int k = 0; k < 64; ++k) {
        const float* ap = sA + k * 65 + ty4;
        float4 bv = *reinterpret_cast<const float4*>(sB + (k << 6) + tx4);
        const float a[4] = {ap[0], ap[1], ap[2], ap[3]};
        const float b[4] = {bv.x, bv.y, bv.z, bv.w};
#pragma unroll
        for (int r = 0; r < 4; ++r)
#pragma unroll
            for (int c = 0; c < 4; ++c)
                acc[r][c] = fmaf(a[r], b[c], acc[r][c]);
    }
}

// ---------------------------------------------------------------------------
// A0: qmean[bh][s][d] = mean_i Q[bh][i][s][d]   (step-0 qbar is j-independent)
// grid 1024, 256 thr
// ---------------------------------------------------------------------------
__global__ void qmean_kernel(const float* __restrict__ Q) {
    int bid = blockIdx.x;
    int bh = bid >> 4;
    int s = ((bid & 15) << 2) + (threadIdx.x >> 6);
    int d = threadIdx.x & 63;
    const float* base = Q + bh * 262144 + s * 64 + d;
    float acc = 0.f;
#pragma unroll 16
    for (int i = 0; i < 64; ++i) acc += base[i * 4096];
    g_qmean[(bh << 6 | s) * 64 + d] = acc * (1.0f / 64.0f);
}

// ---------------------------------------------------------------------------
// A: per (bh,s): w[j] = sum_i L[i][j]; qbar[j][d] = (sum_i L[i][j]Q[i][d])/w[j]
// grid 4096, 256 thr, smem 33024B
// ---------------------------------------------------------------------------
__global__ void qbar_kernel(const float* __restrict__ Q) {
    int bid = blockIdx.x;
    int bh = bid >> 6, s = bid & 63;
    extern __shared__ float sm[];
    float* sL = sm;           // [i][j] stride 64 (reduction i major already)
    float* sQ = sm + 4096;    // [i][d] stride 64
    float* sw = sm + 8192;    // [64] 1/w
    int tid = threadIdx.x;

    const float4* Lb = reinterpret_cast<const float4*>(g_L + ((bh << 6 | s) << 12));
#pragma unroll
    for (int r = 0; r < 4; ++r) {
        int l4 = (r << 8) + tid;
        reinterpret_cast<float4*>(sL)[l4] = Lb[l4];
    }
    const float* Qb = Q + bh * 262144 + s * 64;
#pragma unroll
    for (int r = 0; r < 4; ++r) {
        int l4 = (r << 8) + tid;
        int i = l4 >> 4, d4 = (l4 & 15) << 2;
        reinterpret_cast<float4*>(sQ)[l4] =
            *reinterpret_cast<const float4*>(Qb + i * 4096 + d4);
    }
    __syncthreads();
    if (tid < 64) {
        float acc = 0.f;
#pragma unroll 8
        for (int i = 0; i < 64; ++i) acc += sL[(i << 6) + tid];
        sw[tid] = 1.0f / acc;
    }
    __syncthreads();

    int tx = tid & 15, ty = tid >> 4;
    float acc[4][4] = {};
    mm16<64, 64>(sL, sQ, ty << 2, tx << 2, acc);

    float* ob = g_qbar + bh * 262144 + s * 64 + (tx << 2);
#pragma unroll
    for (int rr = 0; rr < 4; ++rr) {
        int j = (ty << 2) + rr;
        float w = sw[j];
        float4 o = make_float4(acc[rr][0] * w, acc[rr][1] * w, acc[rr][2] * w, acc[rr][3] * w);
        *reinterpret_cast<float4*>(ob + j * 4096) = o;
    }
}

// ---------------------------------------------------------------------------
// B: per (bh,j): S=scale*qbar_j K_j^T; R=softmax_t(S); ent; kbar=R K; (vbar=R V)
// grid 4096, 256 thr, smem 84224B
// ---------------------------------------------------------------------------
__global__ void bstep_kernel(const float* __restrict__ Kg, const float* __restrict__ Vg,
                             int use_qmean, int do_vbar) {
    int bid = blockIdx.x;
    int bh = bid >> 6, j = bid & 63;
    extern __shared__ float sm[];
    float* sQbT = sm;             // [d][s] stride 68
    float* sKT  = sm + 4352;      // [d][t] stride 68
    float* sK   = sm + 8704;      // [t][d] stride 64
    float* sV   = sm + 12800;     // [t][d] stride 64
    float* sRT  = sm + 16896;     // [t][s] stride 65
    int tid = threadIdx.x;

    const float* Kb = Kg + bh * 262144 + j * 4096;
#pragma unroll
    for (int r = 0; r < 16; ++r) {
        int lin = (r << 8) + tid;
        int t = lin >> 6, d = lin & 63;
        float v = Kb[lin];
        sK[lin] = v;
        sKT[d * 68 + t] = v;
    }
    const float* qb = use_qmean ? (g_qmean + (bh << 12))
                                : (g_qbar + bh * 262144 + j * 4096);
#pragma unroll
    for (int r = 0; r < 16; ++r) {
        int lin = (r << 8) + tid;
        int s = lin >> 6, d = lin & 63;
        sQbT[d * 68 + s] = qb[lin];
    }
    if (do_vbar) {
        const float* Vb = Vg + bh * 262144 + j * 4096;
#pragma unroll
        for (int r = 0; r < 4; ++r) {
            int l4 = (r << 8) + tid;
            reinterpret_cast<float4*>(sV)[l4] = reinterpret_cast<const float4*>(Vb)[l4];
        }
    }
    __syncthreads();

    int tx = tid & 15, ty = tid >> 4;
    int tx4 = tx << 2, ty4 = ty << 2;

    float S[4][4] = {};
    mm16<68, 68>(sQbT, sKT, ty4, tx4, S);

    // softmax over t (across tx), R + entropy
    float R[4][4];
#pragma unroll
    for (int rr = 0; rr < 4; ++rr) {
        float mx = -1e30f;
#pragma unroll
        for (int cc = 0; cc < 4; ++cc) { S[rr][cc] *= SCALE; mx = fmaxf(mx, S[rr][cc]); }
        mx = redmax16(mx);
        float p[4], sum = 0.f;
#pragma unroll
        for (int cc = 0; cc < 4; ++cc) { p[cc] = __expf(S[rr][cc] - mx); sum += p[cc]; }
        sum = redsum16(sum);
        float inv = 1.0f / sum;
        float lsum = __logf(sum);
        float e = 0.f;
#pragma unroll
        for (int cc = 0; cc < 4; ++cc) {
            float rv = p[cc] * inv;
            float lr = S[rr][cc] - mx - lsum;
            e += rv * lr;
            R[rr][cc] = rv;
        }
        e = redsum16(e);
        if (tx == 0) g_ent[((bh << 6) + ty4 + rr) * 64 + j] = -e;
    }
#pragma unroll
    for (int rr = 0; rr < 4; ++rr)
#pragma unroll
        for (int cc = 0; cc < 4; ++cc)
            sRT[(tx4 + cc) * 65 + ty4 + rr] = R[rr][cc];
    __syncthreads();

    // kbar[s][d] = sum_t R[s][t] K[t][d]
    float acc[4][4] = {};
    mm16_sa65(sRT, sK, ty4, tx4, acc);
#pragma unroll
    for (int rr = 0; rr < 4; ++rr) {
        int s = ty4 + rr;
        *reinterpret_cast<float4*>(g_kbar + ((bh << 6 | s) << 12) + (j << 6) + tx4) =
            make_float4(acc[rr][0], acc[rr][1], acc[rr][2], acc[rr][3]);
    }

    if (do_vbar) {
        float av[4][4] = {};
        mm16_sa65(sRT, sV, ty4, tx4, av);
#pragma unroll
        for (int rr = 0; rr < 4; ++rr) {
            int s = ty4 + rr;
            *reinterpret_cast<float4*>(g_vbar + ((bh << 6 | s) << 12) + (j << 6) + tx4) =
                make_float4(av[rr][0], av[rr][1], av[rr][2], av[rr][3]);
        }
    }
}

// ---------------------------------------------------------------------------
// C: per (bh,s): SL = scale*Q kbar^T + ent; L = softmax_j; write L or out=L vbar
// grid 4096, 256 thr, smem 68096B
// ---------------------------------------------------------------------------
__global__ void cstep_kernel(const float* __restrict__ Qg, float* __restrict__ out,
                             int is_final) {
    int bid = blockIdx.x;
    int bh = bid >> 6, s = bid & 63;
    extern __shared__ float sm[];
    float* sQT  = sm;             // [d][i] stride 68
    float* sKbT = sm + 4352;      // [d][j] stride 68
    float* sLT  = sm + 8704;      // [j][i] stride 65 (final only)
    float* sVb  = sm + 12864;     // [j][d] stride 64 (final only)
    float* sEnt = sm + 16960;     // [64]
    int tid = threadIdx.x;

    const float* Qb = Qg + bh * 262144 + s * 64;
#pragma unroll
    for (int r = 0; r < 16; ++r) {
        int lin = (r << 8) + tid;
        int i = lin >> 6, d = lin & 63;
        sQT[d * 68 + i] = Qb[i * 4096 + d];
    }
    const float* kb = g_kbar + ((bh << 6 | s) << 12);
#pragma unroll
    for (int r = 0; r < 16; ++r) {
        int lin = (r << 8) + tid;
        int jj = lin >> 6, d = lin & 63;
        sKbT[d * 68 + jj] = kb[lin];
    }
    if (is_final) {
        const float* vb = g_vbar + ((bh << 6 | s) << 12);
#pragma unroll
        for (int r = 0; r < 4; ++r) {
            int l4 = (r << 8) + tid;
            reinterpret_cast<float4*>(sVb)[l4] = reinterpret_cast<const float4*>(vb)[l4];
        }
    }
    if (tid < 64) sEnt[tid] = g_ent[((bh << 6) + s) * 64 + tid];
    __syncthreads();

    int tx = tid & 15, ty = tid >> 4;
    int tx4 = tx << 2, ty4 = ty << 2;

    float S[4][4] = {};
    mm16<68, 68>(sQT, sKbT, ty4, tx4, S);

    float ev[4];
#pragma unroll
    for (int cc = 0; cc < 4; ++cc) ev[cc] = sEnt[tx4 + cc];

    float L[4][4];
#pragma unroll
    for (int rr = 0; rr < 4; ++rr) {
        float mx = -1e30f;
#pragma unroll
        for (int cc = 0; cc < 4; ++cc) {
            S[rr][cc] = S[rr][cc] * SCALE + ev[cc];
            mx = fmaxf(mx, S[rr][cc]);
        }
        mx = redmax16(mx);
        float sum = 0.f;
#pragma unroll
        for (int cc = 0; cc < 4; ++cc) { L[rr][cc] = __expf(S[rr][cc] - mx); sum += L[rr][cc]; }
        sum = redsum16(sum);
        float inv = 1.0f / sum;
#pragma unroll
        for (int cc = 0; cc < 4; ++cc) L[rr][cc] *= inv;
    }

    if (!is_final) {
        float* lb = g_L + ((bh << 6 | s) << 12) + tx4;
#pragma unroll
        for (int rr = 0; rr < 4; ++rr) {
            int i = ty4 + rr;
            *reinterpret_cast<float4*>(lb + (i << 6)) =
                make_float4(L[rr][0], L[rr][1], L[rr][2], L[rr][3]);
        }
    } else {
#pragma unroll
        for (int rr = 0; rr < 4; ++rr)
#pragma unroll
            for (int cc = 0; cc < 4; ++cc)
                sLT[(tx4 + cc) * 65 + ty4 + rr] = L[rr][cc];
        __syncthreads();
        float acc[4][4] = {};
        mm16_sa65(sLT, sVb, ty4, tx4, acc);
        float* ob = out + bh * 262144 + s * 64 + tx4;
#pragma unroll
        for (int rr = 0; rr < 4; ++rr) {
            int i = ty4 + rr;
            *reinterpret_cast<float4*>(ob + i * 4096) =
                make_float4(acc[rr][0], acc[rr][1], acc[rr][2], acc[rr][3]);
        }
    }
}

// ---------------------------------------------------------------------------
extern "C" void kernel_launch(void* const* d_in, const int* in_sizes, int n_in,
                              void* d_out, int out_size) {
    const float* Q = (const float*)d_in[0];
    const float* K = (const float*)d_in[1];
    const float* V = (const float*)d_in[2];
    float* out = (float*)d_out;

    const int SM_A = 8256 * 4;    // 33024
    const int SM_B = 21056 * 4;   // 84224
    const int SM_C = 17024 * 4;   // 68096
    cudaFuncSetAttribute(qbar_kernel,  cudaFuncAttributeMaxDynamicSharedMemorySize, SM_A);
    cudaFuncSetAttribute(bstep_kernel, cudaFuncAttributeMaxDynamicSharedMemorySize, SM_B);
    cudaFuncSetAttribute(cstep_kernel, cudaFuncAttributeMaxDynamicSharedMemorySize, SM_C);

    // step 0
    qmean_kernel<<<1024, 256>>>(Q);
    bstep_kernel<<<4096, 256, SM_B>>>(K, V, 1, 0);
    cstep_kernel<<<4096, 256, SM_C>>>(Q, out, 0);
    // step 1
    qbar_kernel<<<4096, 256, SM_A>>>(Q);
    bstep_kernel<<<4096, 256, SM_B>>>(K, V, 0, 0);
    cstep_kernel<<<4096, 256, SM_C>>>(Q, out, 0);
    // step 2 (B also produces vbar; C fuses final output)
    qbar_kernel<<<4096, 256, SM_A>>>(Q);
    bstep_kernel<<<4096, 256, SM_B>>>(K, V, 0, 1);
    cstep_kernel<<<4096, 256, SM_C>>>(Q, out, 1);
}